// round 12
// baseline (speedup 1.0000x reference)
#include <cuda_runtime.h>
#include <cuda_fp16.h>

#define NN      512
#define MM      512
#define NB      32
#define NBLK    16
#define TILE_H  (MM * NB)      // 16384 halves = 32 KB per tile
#define TPB     512
#define NPROB   256
#define NRES    208            // problems with L2-resident (evict_last) tiles
#define C_ALPHA 0.005f
#define C_SCALE 0.001f
#define C_DELTA 0.1f
#define MAX_UPD 51

// Retiled A (fp16): [prob][tile j][512 rows x 32 cols], row=64B=4 segs of 16B,
// swizzle: logical seg s stored at phys = s ^ ((r>>1)&3).
__device__ __half d_At[(size_t)NPROB * NN * MM];

__device__ __forceinline__ void cp_async16_pol(void* dst_smem, const void* src_gmem,
                                               unsigned long long pol) {
    unsigned d = (unsigned)__cvta_generic_to_shared(dst_smem);
    asm volatile("cp.async.cg.shared.global.L2::cache_hint [%0], [%1], 16, %2;"
                 :: "r"(d), "l"(src_gmem), "l"(pol));
}
__device__ __forceinline__ void cp_commit() { asm volatile("cp.async.commit_group;"); }
__device__ __forceinline__ void cp_wait0()  { asm volatile("cp.async.wait_group 0;"); }
__device__ __forceinline__ void cp_wait1()  { asm volatile("cp.async.wait_group 1;"); }

// ---------------- retile + quantize: fp32 row-major -> fp16 swizzled 32KB tiles ----------
__global__ __launch_bounds__(TPB)
void retile_kernel(const float* __restrict__ Ain) {
    const int p   = blockIdx.x;
    const int tid = threadIdx.x;
    const float* Ap = Ain + (size_t)p * (MM * NN);
    __half* Tp = d_At + (size_t)p * (MM * NN);

    __shared__ __half st[16 * 1024];   // 16 tiles x (32 rows x 32 cols) staged

    for (int rb = 0; rb < 16; rb++) {
#pragma unroll
        for (int i = 0; i < 4; i++) {
            int lin  = i * TPB + tid;
            int rr   = lin >> 6;
            int segi = lin & 63;
            int j    = segi >> 2;
            int s    = segi & 3;
            int r    = rb * 32 + rr;
            const float4* src = (const float4*)(Ap + (size_t)r * NN + j * NB + s * 8);
            float4 a = src[0], b = src[1];
            int phys = s ^ ((r >> 1) & 3);
            __half2* d = (__half2*)(st + j * 1024 + rr * NB + phys * 8);
            d[0] = __floats2half2_rn(a.x, a.y);
            d[1] = __floats2half2_rn(a.z, a.w);
            d[2] = __floats2half2_rn(b.x, b.y);
            d[3] = __floats2half2_rn(b.z, b.w);
        }
        __syncthreads();
#pragma unroll
        for (int i = 0; i < 4; i++) {
            int dlin = i * TPB + tid;
            int j = dlin >> 7;
            int u = dlin & 127;
            uint4 v = ((const uint4*)(st + j * 1024))[u];
            ((uint4*)(Tp + (size_t)j * TILE_H + rb * 1024))[u] = v;
        }
        __syncthreads();
    }
}

// ---------------- main kernel ----------------
extern __shared__ __half smh[];

// thread tid copies ITS OWN ROW (64B) of the tile: per-thread program order
// guarantees the y-pass read of this row precedes the async overwrite.
__device__ __forceinline__ void load_row(__half* dst, const __half* __restrict__ src,
                                         int tid, unsigned long long pol) {
    const __half* s = src + tid * NB;
    __half* d = dst + tid * NB;
#pragma unroll
    for (int i = 0; i < 4; i++)
        cp_async16_pol(d + i * 8, s + i * 8, pol);
    cp_commit();
}

// accumulate one half2 against two x-values into yacc (single fp32 chain)
#define ACCP(u, xv0, xv1) { __half2 _h = *(__half2*)&(u); float2 _f = __half22float2(_h); \
                            yacc = fmaf(_f.x, (xv0), yacc); yacc = fmaf(_f.y, (xv1), yacc); }

#define YSEG(cs, xa, xb) { ACCP((cs).x, (xa).x, (xa).y); ACCP((cs).y, (xa).z, (xa).w); \
                           ACCP((cs).z, (xb).x, (xb).y); ACCP((cs).w, (xb).z, (xb).w); }

#define YPASS(Abase, xqp) { \
    const float4* xq = (const float4*)(xqp); \
    const uint4* rowp = (const uint4*)((Abase) + tid * NB); \
    _Pragma("unroll") \
    for (int s = 0; s < 4; s++) { \
        uint4 cs = rowp[s ^ q2]; \
        float4 xa = xq[2 * s], xb = xq[2 * s + 1]; \
        YSEG(cs, xa, xb); \
    } }

__global__ __launch_bounds__(TPB, 2)
void lva_kernel(const float* __restrict__ xin,
                const float* __restrict__ bin,
                float* __restrict__ xout) {
    const int p   = blockIdx.x;
    const int tid = threadIdx.x;

    __half* sA[3];
    sA[0] = smh;
    sA[1] = sA[0] + TILE_H;
    sA[2] = sA[1] + TILE_H;
    float* sx    = (float*)(sA[2] + TILE_H);   // 512
    float* sviol = sx + NN;                    // 512
    float* spart = sviol + MM;                 // 1024 ([32 phases][32 cols])
    float* sxblk = spart + 1024;               // 64 (double-buffered 2x32)
    float* sred  = sxblk + 64;                 // 32

    const __half* Tp = d_At + (size_t)p * (MM * NN);

    unsigned long long pol;
    if (p < NRES)
        asm("createpolicy.fractional.L2::evict_last.b64 %0, 1.0;" : "=l"(pol));
    else
        asm("createpolicy.fractional.L2::evict_first.b64 %0, 1.0;" : "=l"(pol));

    sx[tid] = xin[p * NN + tid];
    const float breg = bin[p * MM + tid];
    __syncthreads();

    load_row(sA[0], Tp, tid, pol);
    load_row(sA[1], Tp + TILE_H, tid, pol);
    unsigned gl = 2;       // next tile to issue (buffer gl%3, tile gl&15)
    unsigned gcnt = 0;     // tiles consumed

    const int q2   = (tid >> 1) & 3;          // y-pass swizzle key (row = tid)
    const int c2   = tid & 15;                // g-pass column pair (cols 2c2, 2c2+1)
    const int krow = tid >> 4;                // g-pass row phase (0..31)
    const int goff = krow * NB + (((c2 >> 2) ^ ((krow >> 1) & 3)) << 3) + ((c2 & 3) << 1);

    __half2 vr2[16];                          // duplicated viol (fp16) for g-pass
    float yacc = 0.0f;

    // ---------- initial sweep: y = A @ x ----------
    for (int j = 0; j < NBLK; j++) {
        cp_wait1();
        __syncthreads();
        const __half* A = sA[gcnt % 3]; gcnt++;
        YPASS(A, sx + j * NB);
        load_row(sA[gl % 3], Tp + (size_t)(gl & 15) * TILE_H, tid, pol); gl++;
    }

    // ---------- finalize ----------
    float total;
    {
        float v = fmaxf(__fadd_rn(yacc, -breg), 0.0f);
        sviol[tid] = v;
        float t = v;
#pragma unroll
        for (int o = 16; o > 0; o >>= 1) t += __shfl_down_sync(0xffffffffu, t, o);
        if ((tid & 31) == 0) sred[tid >> 5] = t;
        __syncthreads();
        if (tid < 32) {
            float w = (tid < 16) ? sred[tid] : 0.0f;
#pragma unroll
            for (int o = 8; o > 0; o >>= 1) w += __shfl_down_sync(0xffffffffu, w, o);
            if (tid == 0) sred[16] = w;
        }
        __syncthreads();
        total = sred[16];
#pragma unroll
        for (int i = 0; i < 16; i++)
            vr2[i] = __half2half2(__float2half_rn(sviol[krow + 32 * i]));
        yacc = 0.0f;
    }

    // ---------- iterate: ONE __syncthreads per block ----------
    // per block j: [bar] g(j) -> {warps 0-14: arrive; warp 15: sync+upd(j)} -> y(j-1)
    //              -> per-thread row prefetch of tile j+2
    int it = 0;
    while (it < MAX_UPD && total >= C_DELTA) {
        const __half* Aprev = sA[0];   // dummy; unused at j=0

        for (int j = 0; j < NBLK; j++) {
            cp_wait1();
            __syncthreads();           // tile j arrived; sxblk(j-1)/buffer handoff visible
            const __half* A = sA[gcnt % 3];

            // g(j): colpair (2c2,2c2+1), rows krow+32i (fp16 accumulate)
            {
                const __half2* ap = (const __half2*)(A + goff);  // stride 512 half2 per i
                __half2 acc2 = __float2half2_rn(0.0f);
#pragma unroll
                for (int i = 0; i < 16; i++)
                    acc2 = __hfma2(vr2[i], ap[i * 512], acc2);
                float2 gf = __half22float2(acc2);
                spart[krow * NB + 2 * c2]     = gf.x;
                spart[krow * NB + 2 * c2 + 1] = gf.y;
            }

            // asymmetric rendezvous: only warp 15 waits for all g-stores
            if (tid >= 480) {
                asm volatile("bar.sync 1, 512;" ::: "memory");
                // upd(j): this warp's 32 lanes handle the block's 32 columns
                int col = tid - 480;
                float g0 = 0.0f, g1 = 0.0f;
#pragma unroll
                for (int k = 0; k < 16; k++) {
                    g0 += spart[(2 * k) * NB + col];
                    g1 += spart[(2 * k + 1) * NB + col];
                }
                float g   = g0 + g1;
                float xo  = sx[j * NB + col];
                float den = __fadd_rn(1.0f, __fmul_rn(C_SCALE, g));
                float lr  = __fdiv_rn(C_ALPHA, den);
                float xn  = fmaxf(__fsub_rn(xo, __fmul_rn(lr, g)), 0.0f);
                sx[j * NB + col] = xn;
                sxblk[(j & 1) * NB + col] = xn;
            } else {
                asm volatile("bar.arrive 1, 512;" ::: "memory");
            }

            // y(j-1): overlaps warp 15's update
            if (j > 0) YPASS(Aprev, sxblk + ((j - 1) & 1) * NB);

            // prefetch tile j+2 into the buffer y(j-1) just released (own-row order-safe)
            load_row(sA[gl % 3], Tp + (size_t)(gl & 15) * TILE_H, tid, pol); gl++;

            Aprev = A; gcnt++;
        }

        __syncthreads();               // upd(15)'s sxblk visible
        YPASS(Aprev, sxblk + NB);      // y(15), sxblk buffer (15&1)=1

        // finalize
        {
            float v = fmaxf(__fadd_rn(yacc, -breg), 0.0f);
            sviol[tid] = v;
            float t = v;
#pragma unroll
            for (int o = 16; o > 0; o >>= 1) t += __shfl_down_sync(0xffffffffu, t, o);
            if ((tid & 31) == 0) sred[tid >> 5] = t;
            __syncthreads();
            if (tid < 32) {
                float w = (tid < 16) ? sred[tid] : 0.0f;
#pragma unroll
                for (int o = 8; o > 0; o >>= 1) w += __shfl_down_sync(0xffffffffu, w, o);
                if (tid == 0) sred[16] = w;
            }
            __syncthreads();
            total = sred[16];
#pragma unroll
            for (int i = 0; i < 16; i++)
                vr2[i] = __half2half2(__float2half_rn(sviol[krow + 32 * i]));
            yacc = 0.0f;
        }
        it++;
    }

    cp_wait0();
    xout[p * NN + tid] = sx[tid];
}

extern "C" void kernel_launch(void* const* d_in, const int* in_sizes, int n_in,
                              void* d_out, int out_size) {
    // metadata order: x [B,S,N], A [B,S,M,N], b [B,S,M]
    const float* x = (const float*)d_in[0];
    const float* A = (const float*)d_in[1];
    const float* b = (const float*)d_in[2];
    float* out = (float*)d_out;

    if (n_in == 3 && in_sizes[0] > in_sizes[1]) {
        A = (const float*)d_in[0];
        x = (const float*)d_in[1];
    }

    int nprob = out_size / NN;   // 256

    retile_kernel<<<nprob, TPB>>>(A);

    size_t smem_bytes = (size_t)(3 * TILE_H) * sizeof(__half)
                      + (size_t)(NN + MM + 1024 + 64 + 32) * sizeof(float);
    cudaFuncSetAttribute(lva_kernel, cudaFuncAttributeMaxDynamicSharedMemorySize,
                         (int)smem_bytes);
    lva_kernel<<<nprob, TPB, smem_bytes>>>(x, b, out);
}

// round 13
// speedup vs baseline: 1.4563x; 1.4563x over previous
#include <cuda_runtime.h>
#include <cuda_fp16.h>

#define NN      512
#define MM      512
#define NB      32
#define NBLK    16
#define TILE_H  (MM * NB)      // 16384 halves = 32 KB per tile
#define TPB     512
#define NPROB   256
#define NRES    208            // problems with L2-resident (evict_last) tiles
#define C_ALPHA 0.005f
#define C_SCALE 0.001f
#define C_DELTA 0.1f
#define MAX_UPD 51

// Retiled A (fp16): [prob][tile j][512 rows x 32 cols], row=64B=4 segs of 16B,
// swizzle: logical seg s stored at phys = s ^ ((r>>1)&3).
__device__ __half d_At[(size_t)NPROB * NN * MM];

__device__ __forceinline__ void cp_async16_pol(void* dst_smem, const void* src_gmem,
                                               unsigned long long pol) {
    unsigned d = (unsigned)__cvta_generic_to_shared(dst_smem);
    asm volatile("cp.async.cg.shared.global.L2::cache_hint [%0], [%1], 16, %2;"
                 :: "r"(d), "l"(src_gmem), "l"(pol));
}
__device__ __forceinline__ void cp_commit() { asm volatile("cp.async.commit_group;"); }
__device__ __forceinline__ void cp_wait0()  { asm volatile("cp.async.wait_group 0;"); }
__device__ __forceinline__ void cp_wait1()  { asm volatile("cp.async.wait_group 1;"); }

// ---------------- retile + quantize: fp32 row-major -> fp16 swizzled 32KB tiles ----------
__global__ __launch_bounds__(TPB)
void retile_kernel(const float* __restrict__ Ain) {
    const int p   = blockIdx.x;
    const int tid = threadIdx.x;
    const float* Ap = Ain + (size_t)p * (MM * NN);
    __half* Tp = d_At + (size_t)p * (MM * NN);

    __shared__ __half st[16 * 1024];   // 16 tiles x (32 rows x 32 cols) staged

    for (int rb = 0; rb < 16; rb++) {
#pragma unroll
        for (int i = 0; i < 4; i++) {
            int lin  = i * TPB + tid;
            int rr   = lin >> 6;
            int segi = lin & 63;
            int j    = segi >> 2;
            int s    = segi & 3;
            int r    = rb * 32 + rr;
            const float4* src = (const float4*)(Ap + (size_t)r * NN + j * NB + s * 8);
            float4 a = src[0], b = src[1];
            int phys = s ^ ((r >> 1) & 3);
            __half2* d = (__half2*)(st + j * 1024 + rr * NB + phys * 8);
            d[0] = __floats2half2_rn(a.x, a.y);
            d[1] = __floats2half2_rn(a.z, a.w);
            d[2] = __floats2half2_rn(b.x, b.y);
            d[3] = __floats2half2_rn(b.z, b.w);
        }
        __syncthreads();
#pragma unroll
        for (int i = 0; i < 4; i++) {
            int dlin = i * TPB + tid;
            int j = dlin >> 7;
            int u = dlin & 127;
            uint4 v = ((const uint4*)(st + j * 1024))[u];
            ((uint4*)(Tp + (size_t)j * TILE_H + rb * 1024))[u] = v;
        }
        __syncthreads();
    }
}

// ---------------- main kernel ----------------
extern __shared__ __half smh[];

__device__ __forceinline__ void load_tile(__half* dst, const __half* __restrict__ src,
                                          int tid, unsigned long long pol) {
#pragma unroll
    for (int i = 0; i < 4; i++) {
        int lin = i * TPB + tid;
        cp_async16_pol(dst + lin * 8, src + lin * 8, pol);
    }
    cp_commit();
}

// fp32 y-pass (initial sweep only)
#define ACCP(u, xv0, xv1) { __half2 _h = *(__half2*)&(u); float2 _f = __half22float2(_h); \
                            yacc = fmaf(_f.x, (xv0), yacc); yacc = fmaf(_f.y, (xv1), yacc); }
#define YSEG(cs, xa, xb) { ACCP((cs).x, (xa).x, (xa).y); ACCP((cs).y, (xa).z, (xa).w); \
                           ACCP((cs).z, (xb).x, (xb).y); ACCP((cs).w, (xb).z, (xb).w); }
#define YPASS32(Abase, xqp) { \
    const float4* xq = (const float4*)(xqp); \
    const uint4* rowp = (const uint4*)((Abase) + tid * NB); \
    _Pragma("unroll") \
    for (int s = 0; s < 4; s++) { \
        uint4 cs = rowp[s ^ q2]; \
        float4 xa = xq[2 * s], xb = xq[2 * s + 1]; \
        YSEG(cs, xa, xb); \
    } }

// fp16 y-pass (iterate sweeps): A half2s * x half2s, two 8-long HFMA2 chains
#define HSEG(acc, au, xu) { acc = __hfma2(*(__half2*)&(au).x, *(__half2*)&(xu).x, acc); \
                            acc = __hfma2(*(__half2*)&(au).y, *(__half2*)&(xu).y, acc); \
                            acc = __hfma2(*(__half2*)&(au).z, *(__half2*)&(xu).z, acc); \
                            acc = __hfma2(*(__half2*)&(au).w, *(__half2*)&(xu).w, acc); }
#define YPASSH(Abase) { \
    const uint4* xh = (const uint4*)sxh; \
    const uint4* rowp = (const uint4*)((Abase) + tid * NB); \
    __half2 acA = __float2half2_rn(0.0f), acB = __float2half2_rn(0.0f); \
    { uint4 au = rowp[0 ^ q2]; uint4 xu = xh[0]; HSEG(acA, au, xu); } \
    { uint4 au = rowp[1 ^ q2]; uint4 xu = xh[1]; HSEG(acB, au, xu); } \
    { uint4 au = rowp[2 ^ q2]; uint4 xu = xh[2]; HSEG(acA, au, xu); } \
    { uint4 au = rowp[3 ^ q2]; uint4 xu = xh[3]; HSEG(acB, au, xu); } \
    float2 fa = __half22float2(acA); float2 fb = __half22float2(acB); \
    yacc += (fa.x + fa.y) + (fb.x + fb.y); }

__global__ __launch_bounds__(TPB, 2)
void lva_kernel(const float* __restrict__ xin,
                const float* __restrict__ bin,
                float* __restrict__ xout) {
    const int p   = blockIdx.x;
    const int tid = threadIdx.x;

    __half* sA[3];
    sA[0] = smh;
    sA[1] = sA[0] + TILE_H;
    sA[2] = sA[1] + TILE_H;
    float* sx    = (float*)(sA[2] + TILE_H);   // 512
    float* sviol = sx + NN;                    // 512
    float* spart = sviol + MM;                 // 1024 ([32 phases][32 cols])
    float* sred  = spart + 1024;               // 32
    __half* sxh  = (__half*)(sred + 32);       // 32 halves (fp16 broadcast of x-block)

    const __half* Tp = d_At + (size_t)p * (MM * NN);

    unsigned long long pol;
    if (p < NRES)
        asm("createpolicy.fractional.L2::evict_last.b64 %0, 1.0;" : "=l"(pol));
    else
        asm("createpolicy.fractional.L2::evict_first.b64 %0, 1.0;" : "=l"(pol));

    sx[tid] = xin[p * NN + tid];
    const float breg = bin[p * MM + tid];
    __syncthreads();

    load_tile(sA[0], Tp, tid, pol);
    load_tile(sA[1], Tp + TILE_H, tid, pol);
    unsigned gl = 2;       // next tile to issue (buffer gl%3, tile gl&15)
    unsigned gcnt = 0;     // tiles consumed

    const int q2   = (tid >> 1) & 3;          // y-pass swizzle key (row = tid)
    const int c2   = tid & 15;                // g-pass column pair (cols 2c2, 2c2+1)
    const int krow = tid >> 4;                // g-pass row phase (0..31)
    const int goff = krow * NB + (((c2 >> 2) ^ ((krow >> 1) & 3)) << 3) + ((c2 & 3) << 1);

    __half2 vr2[16];                          // duplicated viol (fp16) for g-pass
    float yacc = 0.0f;

    // ---------- initial sweep: y = A @ x (fp32 x) ----------
    for (int j = 0; j < NBLK; j++) {
        cp_wait1();
        __syncthreads();
        load_tile(sA[gl % 3], Tp + (size_t)(gl & 15) * TILE_H, tid, pol); gl++;
        const __half* A = sA[gcnt % 3]; gcnt++;
        YPASS32(A, sx + j * NB);
    }

    // ---------- finalize ----------
    float total;
    {
        float v = fmaxf(__fadd_rn(yacc, -breg), 0.0f);
        sviol[tid] = v;
        float t = v;
#pragma unroll
        for (int o = 16; o > 0; o >>= 1) t += __shfl_down_sync(0xffffffffu, t, o);
        if ((tid & 31) == 0) sred[tid >> 5] = t;
        __syncthreads();
        if (tid < 32) {
            float w = (tid < 16) ? sred[tid] : 0.0f;
#pragma unroll
            for (int o = 8; o > 0; o >>= 1) w += __shfl_down_sync(0xffffffffu, w, o);
            if (tid == 0) sred[16] = w;
        }
        __syncthreads();
        total = sred[16];
#pragma unroll
        for (int i = 0; i < 16; i++)
            vr2[i] = __half2half2(__float2half_rn(sviol[krow + 32 * i]));
        yacc = 0.0f;
    }

    // ---------- iterate: per block [bar] {g(j) || y(j-1)} [bar] {prefetch; upd(j)} ----------
    int it = 0;
    while (it < MAX_UPD && total >= C_DELTA) {
        const __half* Aprev = sA[0];   // dummy init; unused at j=0

        for (int j = 0; j < NBLK; j++) {
            cp_wait1();
            __syncthreads();           // tile j ready; upd(j-1) visible
            const __half* A = sA[gcnt % 3];

            // g(j): colpair (2c2,2c2+1), rows krow+32i (fp16 accumulate, single chain)
            {
                const __half2* ap = (const __half2*)(A + goff);  // stride 512 half2 per i
                __half2 acc2 = __float2half2_rn(0.0f);
#pragma unroll
                for (int i = 0; i < 16; i++)
                    acc2 = __hfma2(vr2[i], ap[i * 512], acc2);
                float2 gf = __half22float2(acc2);
                spart[krow * NB + 2 * c2]     = gf.x;
                spart[krow * NB + 2 * c2 + 1] = gf.y;
            }

            // y(j-1): yacc += Aprev[tid,:] . x'(block j-1)  (fp16 path)
            if (j > 0) YPASSH(Aprev);
            __syncthreads();           // g partials complete; tile j-1 free; sxh consumed

            // phase2: prefetch tile gl (into tile j-1's buffer) + update x(block j)
            load_tile(sA[gl % 3], Tp + (size_t)(gl & 15) * TILE_H, tid, pol); gl++;
            if (tid < NB) {
                float g0 = 0.0f, g1 = 0.0f;
#pragma unroll
                for (int k = 0; k < 16; k++) {
                    g0 += spart[(2 * k) * NB + tid];
                    g1 += spart[(2 * k + 1) * NB + tid];
                }
                float g   = g0 + g1;
                float xo  = sx[j * NB + tid];
                float den = __fadd_rn(1.0f, __fmul_rn(C_SCALE, g));
                float lr  = __fdiv_rn(C_ALPHA, den);
                float xn  = fmaxf(__fsub_rn(xo, __fmul_rn(lr, g)), 0.0f);
                sx[j * NB + tid] = xn;
                sxh[tid] = __float2half_rn(xn);
            }
            Aprev = A; gcnt++;
        }

        __syncthreads();               // upd(15) visible
        YPASSH(Aprev);                 // y(15)

        // finalize
        {
            float v = fmaxf(__fadd_rn(yacc, -breg), 0.0f);
            sviol[tid] = v;
            float t = v;
#pragma unroll
            for (int o = 16; o > 0; o >>= 1) t += __shfl_down_sync(0xffffffffu, t, o);
            if ((tid & 31) == 0) sred[tid >> 5] = t;
            __syncthreads();
            if (tid < 32) {
                float w = (tid < 16) ? sred[tid] : 0.0f;
#pragma unroll
                for (int o = 8; o > 0; o >>= 1) w += __shfl_down_sync(0xffffffffu, w, o);
                if (tid == 0) sred[16] = w;
            }
            __syncthreads();
            total = sred[16];
#pragma unroll
            for (int i = 0; i < 16; i++)
                vr2[i] = __half2half2(__float2half_rn(sviol[krow + 32 * i]));
            yacc = 0.0f;
        }
        it++;
    }

    cp_wait0();
    xout[p * NN + tid] = sx[tid];
}

extern "C" void kernel_launch(void* const* d_in, const int* in_sizes, int n_in,
                              void* d_out, int out_size) {
    // metadata order: x [B,S,N], A [B,S,M,N], b [B,S,M]
    const float* x = (const float*)d_in[0];
    const float* A = (const float*)d_in[1];
    const float* b = (const float*)d_in[2];
    float* out = (float*)d_out;

    if (n_in == 3 && in_sizes[0] > in_sizes[1]) {
        A = (const float*)d_in[0];
        x = (const float*)d_in[1];
    }

    int nprob = out_size / NN;   // 256

    retile_kernel<<<nprob, TPB>>>(A);

    size_t smem_bytes = (size_t)(3 * TILE_H) * sizeof(__half)
                      + (size_t)(NN + MM + 1024 + 32) * sizeof(float)
                      + 64 * sizeof(__half);
    cudaFuncSetAttribute(lva_kernel, cudaFuncAttributeMaxDynamicSharedMemorySize,
                         (int)smem_bytes);
    lva_kernel<<<nprob, TPB, smem_bytes>>>(x, b, out);
}